// round 10
// baseline (speedup 1.0000x reference)
#include <cuda_runtime.h>
#include <cuda_fp16.h>
#include <cstdint>

#define N_NODES 50000
#define NUM_E   1600000
#define IN_F    512
#define OUT_F   128
#define NEG_SLOPE 0.01f
#define INV_T     2.0f   // 1 / TEMPERATURE (0.5)

#define TILE_M   128
#define N_TILES  391                   // ceil(50000/128)
#define KCH      32                    // K per chunk
#define NCHUNK   (IN_F / KCH)          // 16

// smem: rows padded to 80B (conflict-free ldmatrix: 80*r mod 128 covers all 8
// 16B groups). Buffers: Ah[2], Bh[2], Bl[2] of 128 rows x 80B = 10240B each.
#define ROWB     80
#define BUF_SZ   (128 * ROWB)          // 10240
#define GEMM_SMEM (6 * BUF_SZ)         // 61440

// ---------------- scratch (static device globals; no allocations) -----------
__device__ __half   g_Whh[(size_t)N_NODES * OUT_F];     // 12.8 MB (fp16 Wh)
__device__ __half   g_Bh16[(size_t)OUT_F * IN_F];       // 128 KB (B^T hi fp16)
__device__ __half   g_Bl16[(size_t)OUT_F * IN_F];       // 128 KB (B^T lo fp16)
__device__ float    g_u1[IN_F];
__device__ float    g_u2[IN_F];
__device__ float    g_s1[N_NODES];
__device__ float    g_s2[N_NODES];
__device__ int      g_cnt[N_NODES];
__device__ int      g_off[N_NODES + 1];
__device__ int      g_cursor[N_NODES];
__device__ uint2    g_csr[NUM_E];                       // (dst, bits(exp(logit)))
__device__ int      g_bsum[64];
__device__ int      g_boff[64];
__device__ int      g_is64;

// ---------------- helpers ----------------------------------------------------
__device__ __forceinline__ uint32_t smem_u32(const void* p) {
    uint32_t a;
    asm("{ .reg .u64 t; cvta.to.shared.u64 t, %1; cvt.u32.u64 %0, t; }" : "=r"(a) : "l"(p));
    return a;
}
__device__ __forceinline__ void cp_async16(uint32_t dst, const void* src) {
    asm volatile("cp.async.cg.shared.global [%0], [%1], 16;"
                 :: "r"(dst), "l"(__cvta_generic_to_global(src)) : "memory");
}
#define CP_COMMIT() asm volatile("cp.async.commit_group;" ::: "memory")
#define CP_WAIT1()  asm volatile("cp.async.wait_group 1;" ::: "memory")
#define CP_WAIT0()  asm volatile("cp.async.wait_group 0;" ::: "memory")

__device__ __forceinline__ void ldsm_x4(uint32_t* r, uint32_t addr) {
    asm volatile("ldmatrix.sync.aligned.m8n8.x4.shared.b16 {%0,%1,%2,%3}, [%4];"
                 : "=r"(r[0]), "=r"(r[1]), "=r"(r[2]), "=r"(r[3]) : "r"(addr));
}
__device__ __forceinline__ void mma_f16(float* d, const uint32_t* a, const uint32_t* b) {
    asm volatile("mma.sync.aligned.m16n8k16.row.col.f32.f16.f16.f32 "
                 "{%0,%1,%2,%3}, {%4,%5,%6,%7}, {%8,%9}, {%0,%1,%2,%3};"
                 : "+f"(d[0]), "+f"(d[1]), "+f"(d[2]), "+f"(d[3])
                 : "r"(a[0]), "r"(a[1]), "r"(a[2]), "r"(a[3]), "r"(b[0]), "r"(b[1]));
}

__device__ __forceinline__ float leaky_logit(float v) {
    v = (v >= 0.0f) ? v : NEG_SLOPE * v;
    return v * INV_T;
}

// ---------------- u1 = W @ a1, u2 = W @ a2 (warp per k row) -------------------
__global__ __launch_bounds__(256) void u_kernel(const float* __restrict__ W,
                                                const float* __restrict__ a) {
    int k    = blockIdx.x * 8 + (threadIdx.x >> 5);
    int lane = threadIdx.x & 31;
    if (k >= IN_F) return;
    float4 w  = *(const float4*)&W[(size_t)k * OUT_F + lane * 4];
    float4 a1 = *(const float4*)&a[lane * 4];
    float4 a2 = *(const float4*)&a[OUT_F + lane * 4];
    float p1 = w.x * a1.x + w.y * a1.y + w.z * a1.z + w.w * a1.w;
    float p2 = w.x * a2.x + w.y * a2.y + w.z * a2.z + w.w * a2.w;
    #pragma unroll
    for (int o = 16; o; o >>= 1) {
        p1 += __shfl_down_sync(0xFFFFFFFFu, p1, o);
        p2 += __shfl_down_sync(0xFFFFFFFFu, p2, o);
    }
    if (lane == 0) { g_u1[k] = p1; g_u2[k] = p2; }
}

// ---------------- s1 = h @ u1, s2 = h @ u2 (warp per row) ---------------------
__global__ __launch_bounds__(256) void matvec_kernel(const float* __restrict__ h) {
    __shared__ float su1[IN_F], su2[IN_F];
    int tid = threadIdx.x;
    if (tid < IN_F / 2) {
        ((float2*)su1)[tid] = ((const float2*)g_u1)[tid];
        ((float2*)su2)[tid] = ((const float2*)g_u2)[tid];
    }
    __syncthreads();
    int row  = blockIdx.x * 8 + (tid >> 5);
    int lane = tid & 31;
    if (row >= N_NODES) return;
    float p1 = 0.f, p2 = 0.f;
    #pragma unroll
    for (int i = 0; i < 4; i++) {
        int col = i * 128 + lane * 4;
        float4 v  = __ldg((const float4*)&h[(size_t)row * IN_F + col]);
        float4 q1 = *(const float4*)&su1[col];
        float4 q2 = *(const float4*)&su2[col];
        p1 += v.x * q1.x + v.y * q1.y + v.z * q1.z + v.w * q1.w;
        p2 += v.x * q2.x + v.y * q2.y + v.z * q2.z + v.w * q2.w;
    }
    #pragma unroll
    for (int o = 16; o; o >>= 1) {
        p1 += __shfl_down_sync(0xFFFFFFFFu, p1, o);
        p2 += __shfl_down_sync(0xFFFFFFFFu, p2, o);
    }
    if (lane == 0) { g_s1[row] = p1; g_s2[row] = p2; }
}

// ---------------- W -> B^T fp16 hi/lo split ------------------------------------
__global__ __launch_bounds__(256) void convert_w_kernel(const float* __restrict__ W) {
    int idx = blockIdx.x * 256 + threadIdx.x;
    if (idx >= OUT_F * (IN_F / 8)) return;
    int n  = idx / (IN_F / 8);
    int k8 = (idx % (IN_F / 8)) * 8;
    unsigned short hb[8], lb[8];
    #pragma unroll
    for (int j = 0; j < 8; j++) {
        float v = W[(size_t)(k8 + j) * OUT_F + n];
        __half hv = __float2half_rn(v);
        __half lv = __float2half_rn(v - __half2float(hv));
        hb[j] = *(unsigned short*)&hv;
        lb[j] = *(unsigned short*)&lv;
    }
    uint4 qh, ql;
    qh.x = hb[0] | ((uint32_t)hb[1] << 16); qh.y = hb[2] | ((uint32_t)hb[3] << 16);
    qh.z = hb[4] | ((uint32_t)hb[5] << 16); qh.w = hb[6] | ((uint32_t)hb[7] << 16);
    ql.x = lb[0] | ((uint32_t)lb[1] << 16); ql.y = lb[2] | ((uint32_t)lb[3] << 16);
    ql.z = lb[4] | ((uint32_t)lb[5] << 16); ql.w = lb[6] | ((uint32_t)lb[7] << 16);
    size_t off = (size_t)n * IN_F + k8;
    *(uint4*)&g_Bh16[off] = qh;
    *(uint4*)&g_Bl16[off] = ql;
}

// ---------------- GEMM: Wh(fp16) = h @ (Bh + Bl), inline A convert ------------
// Reads fp32 h directly: LDG -> convert fp16 in regs -> STS (80B-stride smem).
__global__ __launch_bounds__(256, 2) void gemm_f16_kernel(const float* __restrict__ h) {
    extern __shared__ char smx[];
    const int tid  = threadIdx.x;
    const int lane = tid & 31, wid = tid >> 5;
    const int warp_m = wid & 3, warp_n = wid >> 2;   // 4 x 2 warp grid
    const int tileRow = blockIdx.x * TILE_M;
    const uint32_t sbase = smem_u32(smx);
    // buffer bases: Ah[0],Ah[1],Bh[0],Bh[1],Bl[0],Bl[1]
    const uint32_t AB0 = sbase, AB1 = sbase + BUF_SZ;
    const uint32_t BH0 = sbase + 2 * BUF_SZ, BH1 = sbase + 3 * BUF_SZ;
    const uint32_t BL0 = sbase + 4 * BUF_SZ, BL1 = sbase + 5 * BUF_SZ;

    float acc[2][8][4];
    #pragma unroll
    for (int mt = 0; mt < 2; mt++)
        #pragma unroll
        for (int nt = 0; nt < 8; nt++)
            #pragma unroll
            for (int q = 0; q < 4; q++) acc[mt][nt][q] = 0.0f;

    const int aRow = tid >> 1, aHs = tid & 1;   // 2 threads per A row
    const bool aValid = (tileRow + aRow) < N_NODES;
    const float* aSrcBase = h + (size_t)(tileRow + aRow) * IN_F + aHs * 16;

    uint32_t areg[8];
    auto prefetchA = [&](int c) {
        if (aValid) {
            const float4* p = (const float4*)(aSrcBase + c * KCH);
            #pragma unroll
            for (int j = 0; j < 4; j++) {
                float4 v = __ldg(p + j);
                __half2 h0 = __floats2half2_rn(v.x, v.y);
                __half2 h1 = __floats2half2_rn(v.z, v.w);
                areg[2 * j]     = *(uint32_t*)&h0;
                areg[2 * j + 1] = *(uint32_t*)&h1;
            }
        } else {
            #pragma unroll
            for (int j = 0; j < 8; j++) areg[j] = 0u;
        }
    };
    auto stsA = [&](uint32_t abuf) {
        uint32_t dst = abuf + aRow * ROWB + aHs * 32;
        asm volatile("st.shared.v4.b32 [%0], {%1,%2,%3,%4};"
                     :: "r"(dst), "r"(areg[0]), "r"(areg[1]), "r"(areg[2]), "r"(areg[3]));
        asm volatile("st.shared.v4.b32 [%0], {%1,%2,%3,%4};"
                     :: "r"(dst + 16), "r"(areg[4]), "r"(areg[5]), "r"(areg[6]), "r"(areg[7]));
    };
    auto issueB = [&](int c, uint32_t bhbuf, uint32_t blbuf) {
        #pragma unroll
        for (int i = 0; i < 2; i++) {
            int cid = tid + i * 256;            // 0..511
            int row = cid >> 2, cc = cid & 3;   // 128 rows x 4 x 16B
            cp_async16(bhbuf + row * ROWB + cc * 16,
                       g_Bh16 + (size_t)row * IN_F + c * KCH + cc * 8);
            cp_async16(blbuf + row * ROWB + cc * 16,
                       g_Bl16 + (size_t)row * IN_F + c * KCH + cc * 8);
        }
    };

    const int mi = lane >> 3, r8 = lane & 7;    // ldmatrix lane decomposition

    prefetchA(0);
    issueB(0, BH0, BL0);
    CP_COMMIT();

    for (int c = 0; c < NCHUNK; c++) {
        const int s = c & 1;
        const uint32_t abuf = s ? AB1 : AB0;
        const uint32_t bh   = s ? BH1 : BH0;
        const uint32_t bl   = s ? BL1 : BL0;

        stsA(abuf);
        if (c + 1 < NCHUNK) {
            prefetchA(c + 1);
            issueB(c + 1, (s ? BH0 : BH1), (s ? BL0 : BL1));
            CP_COMMIT();
            CP_WAIT1();
        } else {
            CP_WAIT0();
        }
        __syncthreads();

        #pragma unroll
        for (int kb = 0; kb < 2; kb++) {
            uint32_t a[2][4];
            #pragma unroll
            for (int mt = 0; mt < 2; mt++) {
                int arow = warp_m * 32 + mt * 16 + r8 + (mi & 1) * 8;
                int ac   = kb * 2 + (mi >> 1);
                ldsm_x4(a[mt], abuf + arow * ROWB + ac * 16);
            }
            #pragma unroll
            for (int p = 0; p < 2; p++) {       // Bh then Bl
                uint32_t bBase = p ? bl : bh;
                uint32_t b[8][2];
                #pragma unroll
                for (int np = 0; np < 4; np++) {
                    int brow = warp_n * 64 + np * 16 + (mi >> 1) * 8 + r8;
                    int bc   = kb * 2 + (mi & 1);
                    uint32_t r[4];
                    ldsm_x4(r, bBase + brow * ROWB + bc * 16);
                    b[np * 2][0]     = r[0]; b[np * 2][1]     = r[1];
                    b[np * 2 + 1][0] = r[2]; b[np * 2 + 1][1] = r[3];
                }
                #pragma unroll
                for (int mt = 0; mt < 2; mt++)
                    #pragma unroll
                    for (int nt = 0; nt < 8; nt++)
                        mma_f16(acc[mt][nt], a[mt], b[nt]);
            }
        }
        __syncthreads();
    }

    int row0 = tileRow + warp_m * 32 + (lane >> 2);
    int col0 = warp_n * 64 + (lane & 3) * 2;
    #pragma unroll
    for (int mt = 0; mt < 2; mt++) {
        int r = row0 + mt * 16;
        #pragma unroll
        for (int nt = 0; nt < 8; nt++) {
            int cc = col0 + nt * 8;
            if (r < N_NODES)
                *(__half2*)&g_Whh[(size_t)r * OUT_F + cc] =
                    __floats2half2_rn(acc[mt][nt][0], acc[mt][nt][1]);
            if (r + 8 < N_NODES)
                *(__half2*)&g_Whh[(size_t)(r + 8) * OUT_F + cc] =
                    __floats2half2_rn(acc[mt][nt][2], acc[mt][nt][3]);
        }
    }
}

// ---------------- dtype detection + CSR side branch ---------------------------
__global__ void detect_kernel(const int* __restrict__ ei) {
    __shared__ int any;
    if (threadIdx.x == 0) any = 0;
    __syncthreads();
    for (int i = threadIdx.x; i < 2048; i += blockDim.x)
        if (ei[2 * i + 1] != 0) any = 1;
    __syncthreads();
    if (threadIdx.x == 0) g_is64 = any ? 0 : 1;
}

__global__ void init_cnt_kernel() {
    int i = blockIdx.x * blockDim.x + threadIdx.x;
    if (i < N_NODES) g_cnt[i] = 0;
}

__device__ __forceinline__ void load_edge(const void* ei, int e, int& s, int& d) {
    if (g_is64) {
        const long long* p = (const long long*)ei;
        s = (int)p[e];
        d = (int)p[NUM_E + e];
    } else {
        const int* p = (const int*)ei;
        s = p[e];
        d = p[NUM_E + e];
    }
}

__global__ __launch_bounds__(256) void hist_kernel(const void* __restrict__ ei) {
    int e = blockIdx.x * blockDim.x + threadIdx.x;
    if (e >= NUM_E) return;
    int s, d;
    load_edge(ei, e, s, d);
    atomicAdd(&g_cnt[s], 1);
}

__global__ __launch_bounds__(256) void scan_reduce_kernel() {
    __shared__ int ws[8];
    int tid = threadIdx.x, lane = tid & 31, wid = tid >> 5;
    int s = 0;
    #pragma unroll
    for (int j = 0; j < 4; j++) {
        int i = blockIdx.x * 1024 + j * 256 + tid;
        if (i < N_NODES) s += g_cnt[i];
    }
    #pragma unroll
    for (int o = 16; o; o >>= 1) s += __shfl_xor_sync(0xFFFFFFFFu, s, o);
    if (lane == 0) ws[wid] = s;
    __syncthreads();
    if (tid == 0) {
        int t = 0;
        #pragma unroll
        for (int w = 0; w < 8; w++) t += ws[w];
        g_bsum[blockIdx.x] = t;
    }
}

__global__ void scan_mid_kernel() {
    __shared__ int w0sum;
    int t = threadIdx.x;            // 64 threads
    int lane = t & 31, w = t >> 5;
    const int NBLK = (N_NODES + 1023) / 1024;   // 49
    int v = (t < NBLK) ? g_bsum[t] : 0;
    int x = v;
    #pragma unroll
    for (int o = 1; o < 32; o <<= 1) {
        int y = __shfl_up_sync(0xFFFFFFFFu, x, o);
        if (lane >= o) x += y;
    }
    if (w == 0 && lane == 31) w0sum = x;
    __syncthreads();
    int incl = x + (w == 1 ? w0sum : 0);
    if (t < NBLK) g_boff[t] = incl - v;   // exclusive
}

__global__ __launch_bounds__(1024) void scan_final_kernel() {
    __shared__ int warpsum[32];
    int tid = threadIdx.x, lane = tid & 31, wid = tid >> 5;
    int i = blockIdx.x * 1024 + tid;
    int v = (i < N_NODES) ? g_cnt[i] : 0;
    int x = v;
    #pragma unroll
    for (int o = 1; o < 32; o <<= 1) {
        int y = __shfl_up_sync(0xFFFFFFFFu, x, o);
        if (lane >= o) x += y;
    }
    if (lane == 31) warpsum[wid] = x;
    __syncthreads();
    if (wid == 0) {
        int s = warpsum[lane];
        #pragma unroll
        for (int o = 1; o < 32; o <<= 1) {
            int y = __shfl_up_sync(0xFFFFFFFFu, s, o);
            if (lane >= o) s += y;
        }
        warpsum[lane] = s;
    }
    __syncthreads();
    int base = (wid > 0) ? warpsum[wid - 1] : 0;
    int excl = g_boff[blockIdx.x] + base + x - v;
    if (i < N_NODES) {
        g_off[i]    = excl;
        g_cursor[i] = excl;
    }
    if (blockIdx.x == 0 && tid == 0) g_off[N_NODES] = NUM_E;
}

// fill: packed CSR record (dst, bits(exp(logit)))
__global__ __launch_bounds__(256) void fill_kernel(const void* __restrict__ ei) {
    int e = blockIdx.x * blockDim.x + threadIdx.x;
    if (e >= NUM_E) return;
    int s, d;
    load_edge(ei, e, s, d);
    float lg  = leaky_logit(__ldg(&g_s1[s]) + __ldg(&g_s2[d]));
    int   pos = atomicAdd(&g_cursor[s], 1);
    g_csr[pos] = make_uint2((unsigned)d, __float_as_uint(__expf(lg)));
}

// ---------------- aggregate: warp per node, 8-lane group per edge -------------
// lane = g*8 + l8; lane covers feats [l8*16, l8*16+16) = 32B (2x LDG.128);
// groups 0..3 take edge slots 4j+g -> 4 edges in flight, chain 8 per batch.
__global__ __launch_bounds__(256) void agg_kernel(float* __restrict__ out) {
    int src  = blockIdx.x * 8 + (threadIdx.x >> 5);
    if (src >= N_NODES) return;
    int lane = threadIdx.x & 31;
    int l8   = lane & 7;
    int g    = lane >> 3;
    int beg  = g_off[src];
    int end  = g_off[src + 1];

    float4* out4 = (float4*)out;
    if (beg == end) {
        if (lane < 8) {
            #pragma unroll
            for (int k = 0; k < 4; k++)
                out4[(size_t)src * 32 + l8 * 4 + k] = make_float4(0.f, 0.f, 0.f, 0.f);
        }
        return;
    }

    float acc[16];
    #pragma unroll
    for (int i = 0; i < 16; i++) acc[i] = 0.0f;
    float den = 0.f;

    for (int base = beg; base < end; base += 32) {
        int  idx   = base + lane;
        bool valid = idx < end;
        uint2 rec = valid ? __ldg(&g_csr[idx]) : make_uint2(0u, 0u);
        int   dn  = (int)rec.x;
        float w   = valid ? __uint_as_float(rec.y) : 0.0f;
        den += w;
        int cnt = min(end - base, 32);
        #pragma unroll
        for (int j = 0; j < 8; j++) {
            int   sl = j * 4 + g;
            int   dj = __shfl_sync(0xFFFFFFFFu, dn, sl);
            float wj = __shfl_sync(0xFFFFFFFFu, w,  sl);
            if (sl < cnt) {
                const uint4* p = (const uint4*)&g_Whh[(size_t)dj * OUT_F + l8 * 16];
                uint4 u0 = __ldg(p);
                uint4 u1 = __ldg(p + 1);
                float2 f;
                f = __half22float2(*(__half2*)&u0.x); acc[0] += wj * f.x; acc[1] += wj * f.y;
                f = __half22float2(*(__half2*)&u0.y); acc[2] += wj * f.x; acc[3] += wj * f.y;
                f = __half22float2(*(__half2*)&u0.z); acc[4] += wj * f.x; acc[5] += wj * f.y;
                f = __half22float2(*(__half2*)&u0.w); acc[6] += wj * f.x; acc[7] += wj * f.y;
                f = __half22float2(*(__half2*)&u1.x); acc[8] += wj * f.x; acc[9] += wj * f.y;
                f = __half22float2(*(__half2*)&u1.y); acc[10] += wj * f.x; acc[11] += wj * f.y;
                f = __half22float2(*(__half2*)&u1.z); acc[12] += wj * f.x; acc[13] += wj * f.y;
                f = __half22float2(*(__half2*)&u1.w); acc[14] += wj * f.x; acc[15] += wj * f.y;
            }
        }
    }

    // combine the 4 groups (same features, disjoint edge subsets)
    #pragma unroll
    for (int i = 0; i < 16; i++) {
        acc[i] += __shfl_xor_sync(0xFFFFFFFFu, acc[i], 8);
        acc[i] += __shfl_xor_sync(0xFFFFFFFFu, acc[i], 16);
    }
    #pragma unroll
    for (int o = 16; o; o >>= 1)
        den += __shfl_xor_sync(0xFFFFFFFFu, den, o);
    float inv = (den > 0.0f) ? (1.0f / den) : 0.0f;

    if (lane < 8) {
        #pragma unroll
        for (int k = 0; k < 4; k++) {
            float4 r;
            r.x = fmaxf(acc[4 * k + 0] * inv, 0.0f);
            r.y = fmaxf(acc[4 * k + 1] * inv, 0.0f);
            r.z = fmaxf(acc[4 * k + 2] * inv, 0.0f);
            r.w = fmaxf(acc[4 * k + 3] * inv, 0.0f);
            out4[(size_t)src * 32 + l8 * 4 + k] = r;
        }
    }
}

// ---------------- launch ------------------------------------------------------
extern "C" void kernel_launch(void* const* d_in, const int* in_sizes, int n_in,
                              void* d_out, int out_size) {
    const float* h  = (const float*)d_in[0];
    const float* W  = (const float*)d_in[1];
    const float* a  = (const float*)d_in[2];
    const void*  ei = d_in[3];
    float* out = (float*)d_out;

    static cudaStream_t s2 = nullptr, s3 = nullptr;
    static cudaEvent_t evFork = nullptr, evJoin = nullptr, evMv = nullptr;
    if (s2 == nullptr) {
        cudaStreamCreateWithFlags(&s2, cudaStreamNonBlocking);
        cudaStreamCreateWithFlags(&s3, cudaStreamNonBlocking);
        cudaEventCreateWithFlags(&evFork, cudaEventDisableTiming);
        cudaEventCreateWithFlags(&evJoin, cudaEventDisableTiming);
        cudaEventCreateWithFlags(&evMv, cudaEventDisableTiming);
        cudaFuncSetAttribute(gemm_f16_kernel,
                             cudaFuncAttributeMaxDynamicSharedMemorySize, GEMM_SMEM);
    }

    const int NBLK = (N_NODES + 1023) / 1024;   // 49

    cudaEventRecord(evFork, 0);
    cudaStreamWaitEvent(s2, evFork, 0);
    cudaStreamWaitEvent(s3, evFork, 0);

    // s3: s1/s2 via associativity (u = W@a, s = h@u)
    u_kernel<<<(IN_F + 7) / 8, 256, 0, s3>>>(W, a);
    matvec_kernel<<<(N_NODES + 7) / 8, 256, 0, s3>>>(h);
    cudaEventRecord(evMv, s3);

    // s2: CSR build, then fill once s1/s2 ready
    detect_kernel<<<1, 256, 0, s2>>>((const int*)ei);
    init_cnt_kernel<<<(N_NODES + 255) / 256, 256, 0, s2>>>();
    hist_kernel<<<(NUM_E + 255) / 256, 256, 0, s2>>>(ei);
    scan_reduce_kernel<<<NBLK, 256, 0, s2>>>();
    scan_mid_kernel<<<1, 64, 0, s2>>>();
    scan_final_kernel<<<NBLK, 1024, 0, s2>>>();
    cudaStreamWaitEvent(s2, evMv, 0);
    fill_kernel<<<(NUM_E + 255) / 256, 256, 0, s2>>>(ei);
    cudaEventRecord(evJoin, s2);

    // main: W convert + inline-convert GEMM (overlaps whole side branch)
    convert_w_kernel<<<(OUT_F * (IN_F / 8) + 255) / 256, 256>>>(W);
    gemm_f16_kernel<<<N_TILES, 256, GEMM_SMEM>>>(h);

    // join, then aggregate
    cudaStreamWaitEvent(0, evJoin, 0);
    agg_kernel<<<(N_NODES + 7) / 8, 256>>>(out);
}

// round 11
// speedup vs baseline: 1.0941x; 1.0941x over previous
#include <cuda_runtime.h>
#include <cuda_fp16.h>
#include <cstdint>

#define N_NODES 50000
#define NUM_E   1600000
#define IN_F    512
#define OUT_F   128
#define NEG_SLOPE 0.01f
#define INV_T     2.0f   // 1 / TEMPERATURE (0.5)

#define TILE_M   128
#define N_TILES  391                   // ceil(50000/128)
#define PAD_ROWS (N_TILES * TILE_M)    // 50048
#define GBK      64                    // K per chunk
#define NCHUNK   (IN_F / GBK)          // 8

// smem: stage = [ A 16K | Bh 16K | Bl 16K ] fp16 swizzled; double buffered
#define SBH_OFF     16384
#define SBL_OFF     32768
#define STAGE_BYTES 49152
#define GEMM_SMEM   (2 * STAGE_BYTES)  // 96 KB -> 2 CTAs/SM

// ---------------- scratch (static device globals; no allocations) -----------
__device__ __half   g_Whh[(size_t)N_NODES * OUT_F];     // 12.8 MB (fp16 Wh)
__device__ __half   g_A16[(size_t)PAD_ROWS * IN_F];     // 51.2 MB (fp16 h)
__device__ __half   g_Bh16[(size_t)OUT_F * IN_F];       // 128 KB (B^T hi fp16)
__device__ __half   g_Bl16[(size_t)OUT_F * IN_F];       // 128 KB (B^T lo fp16)
__device__ float    g_u1[IN_F];
__device__ float    g_u2[IN_F];
__device__ float    g_s1[N_NODES];
__device__ float    g_s2[N_NODES];
__device__ int      g_cnt[N_NODES];
__device__ int      g_off[N_NODES + 1];
__device__ int      g_cursor[N_NODES];
__device__ uint2    g_csr[NUM_E];                       // (dst, bits(exp(logit)))
__device__ int      g_bsum[64];
__device__ int      g_boff[64];
__device__ int      g_is64;

// ---------------- helpers ----------------------------------------------------
__device__ __forceinline__ uint32_t smem_u32(const void* p) {
    uint32_t a;
    asm("{ .reg .u64 t; cvta.to.shared.u64 t, %1; cvt.u32.u64 %0, t; }" : "=r"(a) : "l"(p));
    return a;
}
__device__ __forceinline__ void cp_async16(uint32_t dst, const void* src) {
    asm volatile("cp.async.cg.shared.global [%0], [%1], 16;"
                 :: "r"(dst), "l"(__cvta_generic_to_global(src)) : "memory");
}
#define CP_COMMIT() asm volatile("cp.async.commit_group;" ::: "memory")
#define CP_WAIT1()  asm volatile("cp.async.wait_group 1;" ::: "memory")

__device__ __forceinline__ void ldsm_x4(uint32_t* r, uint32_t addr) {
    asm volatile("ldmatrix.sync.aligned.m8n8.x4.shared.b16 {%0,%1,%2,%3}, [%4];"
                 : "=r"(r[0]), "=r"(r[1]), "=r"(r[2]), "=r"(r[3]) : "r"(addr));
}
__device__ __forceinline__ void mma_f16(float* d, const uint32_t* a, const uint32_t* b) {
    asm volatile("mma.sync.aligned.m16n8k16.row.col.f32.f16.f16.f32 "
                 "{%0,%1,%2,%3}, {%4,%5,%6,%7}, {%8,%9}, {%0,%1,%2,%3};"
                 : "+f"(d[0]), "+f"(d[1]), "+f"(d[2]), "+f"(d[3])
                 : "r"(a[0]), "r"(a[1]), "r"(a[2]), "r"(a[3]), "r"(b[0]), "r"(b[1]));
}

__device__ __forceinline__ float leaky_logit(float v) {
    v = (v >= 0.0f) ? v : NEG_SLOPE * v;
    return v * INV_T;
}

// ---------------- u1 = W @ a1, u2 = W @ a2 (warp per k row) -------------------
__global__ __launch_bounds__(256) void u_kernel(const float* __restrict__ W,
                                                const float* __restrict__ a) {
    int k    = blockIdx.x * 8 + (threadIdx.x >> 5);
    int lane = threadIdx.x & 31;
    if (k >= IN_F) return;
    float4 w  = *(const float4*)&W[(size_t)k * OUT_F + lane * 4];
    float4 a1 = *(const float4*)&a[lane * 4];
    float4 a2 = *(const float4*)&a[OUT_F + lane * 4];
    float p1 = w.x * a1.x + w.y * a1.y + w.z * a1.z + w.w * a1.w;
    float p2 = w.x * a2.x + w.y * a2.y + w.z * a2.z + w.w * a2.w;
    #pragma unroll
    for (int o = 16; o; o >>= 1) {
        p1 += __shfl_down_sync(0xFFFFFFFFu, p1, o);
        p2 += __shfl_down_sync(0xFFFFFFFFu, p2, o);
    }
    if (lane == 0) { g_u1[k] = p1; g_u2[k] = p2; }
}

// ---------------- fused: h -> fp16 A16  AND  s1/s2 = h@u1, h@u2 ---------------
__global__ __launch_bounds__(256) void convmv_kernel(const float* __restrict__ h) {
    __shared__ float su1[IN_F], su2[IN_F];
    int tid = threadIdx.x;
    if (tid < IN_F / 2) {
        ((float2*)su1)[tid] = ((const float2*)g_u1)[tid];
        ((float2*)su2)[tid] = ((const float2*)g_u2)[tid];
    }
    __syncthreads();
    int row  = blockIdx.x * 8 + (tid >> 5);
    int lane = tid & 31;
    if (row >= PAD_ROWS) return;

    if (row >= N_NODES) {   // zero padded rows
        #pragma unroll
        for (int i = 0; i < 4; i++)
            *(uint2*)&g_A16[(size_t)row * IN_F + i * 128 + lane * 4] = make_uint2(0, 0);
        return;
    }

    float p1 = 0.f, p2 = 0.f;
    #pragma unroll
    for (int i = 0; i < 4; i++) {
        int col = i * 128 + lane * 4;
        float4 v  = __ldg((const float4*)&h[(size_t)row * IN_F + col]);
        float4 q1 = *(const float4*)&su1[col];
        float4 q2 = *(const float4*)&su2[col];
        p1 += v.x * q1.x + v.y * q1.y + v.z * q1.z + v.w * q1.w;
        p2 += v.x * q2.x + v.y * q2.y + v.z * q2.z + v.w * q2.w;
        __half2 h0 = __floats2half2_rn(v.x, v.y);
        __half2 h1 = __floats2half2_rn(v.z, v.w);
        uint2 q; q.x = *(uint32_t*)&h0; q.y = *(uint32_t*)&h1;
        *(uint2*)&g_A16[(size_t)row * IN_F + col] = q;
    }
    #pragma unroll
    for (int o = 16; o; o >>= 1) {
        p1 += __shfl_down_sync(0xFFFFFFFFu, p1, o);
        p2 += __shfl_down_sync(0xFFFFFFFFu, p2, o);
    }
    if (lane == 0) { g_s1[row] = p1; g_s2[row] = p2; }
}

// ---------------- W -> B^T fp16 hi/lo split ------------------------------------
__global__ __launch_bounds__(256) void convert_w_kernel(const float* __restrict__ W) {
    int idx = blockIdx.x * 256 + threadIdx.x;
    if (idx >= OUT_F * (IN_F / 8)) return;
    int n  = idx / (IN_F / 8);
    int k8 = (idx % (IN_F / 8)) * 8;
    unsigned short hb[8], lb[8];
    #pragma unroll
    for (int j = 0; j < 8; j++) {
        float v = W[(size_t)(k8 + j) * OUT_F + n];
        __half hv = __float2half_rn(v);
        __half lv = __float2half_rn(v - __half2float(hv));
        hb[j] = *(unsigned short*)&hv;
        lb[j] = *(unsigned short*)&lv;
    }
    uint4 qh, ql;
    qh.x = hb[0] | ((uint32_t)hb[1] << 16); qh.y = hb[2] | ((uint32_t)hb[3] << 16);
    qh.z = hb[4] | ((uint32_t)hb[5] << 16); qh.w = hb[6] | ((uint32_t)hb[7] << 16);
    ql.x = lb[0] | ((uint32_t)lb[1] << 16); ql.y = lb[2] | ((uint32_t)lb[3] << 16);
    ql.z = lb[4] | ((uint32_t)lb[5] << 16); ql.w = lb[6] | ((uint32_t)lb[7] << 16);
    size_t off = (size_t)n * IN_F + k8;
    *(uint4*)&g_Bh16[off] = qh;
    *(uint4*)&g_Bl16[off] = ql;
}

// ---------------- GEMM: Wh(fp16) = A16 @ (Bh + Bl) ----------------------------
__global__ __launch_bounds__(256, 2) void gemm_f16_kernel() {
    extern __shared__ char smx[];
    const int tid  = threadIdx.x;
    const int lane = tid & 31, wid = tid >> 5;
    const int warp_m = wid & 3, warp_n = wid >> 2;   // 4 x 2 warp grid
    const int tileRow = blockIdx.x * TILE_M;
    const uint32_t sbase = smem_u32(smx);

    float acc[2][8][4];
    #pragma unroll
    for (int mt = 0; mt < 2; mt++)
        #pragma unroll
        for (int nt = 0; nt < 8; nt++)
            #pragma unroll
            for (int q = 0; q < 4; q++) acc[mt][nt][q] = 0.0f;

    auto load_stage = [&](int stage, int c) {
        int k0 = c * GBK;
        uint32_t sS = sbase + stage * STAGE_BYTES;
        #pragma unroll
        for (int i = 0; i < 4; i++) {
            int cid = tid + i * 256;            // 0..1023
            int row = cid >> 3, cc = cid & 7;
            uint32_t sw = (uint32_t)((cc ^ (row & 7)) << 4);
            cp_async16(sS + row * 128 + sw,
                       g_A16 + (size_t)(tileRow + row) * IN_F + k0 + cc * 8);
            cp_async16(sS + SBH_OFF + row * 128 + sw,
                       g_Bh16 + (size_t)row * IN_F + k0 + cc * 8);
            cp_async16(sS + SBL_OFF + row * 128 + sw,
                       g_Bl16 + (size_t)row * IN_F + k0 + cc * 8);
        }
    };

    load_stage(0, 0);
    CP_COMMIT();

    const int mi = lane >> 3, r8 = lane & 7;

    for (int c = 0; c < NCHUNK; c++) {
        if (c + 1 < NCHUNK) load_stage((c + 1) & 1, c + 1);
        CP_COMMIT();
        CP_WAIT1();
        __syncthreads();

        uint32_t sS = sbase + (c & 1) * STAGE_BYTES;

        #pragma unroll
        for (int ks = 0; ks < 4; ks++) {
            uint32_t a[2][4];
            #pragma unroll
            for (int mt = 0; mt < 2; mt++) {
                int arow = warp_m * 32 + mt * 16 + r8 + (mi & 1) * 8;
                int ac   = ks * 2 + (mi >> 1);
                ldsm_x4(a[mt], sS + arow * 128 + ((ac ^ (arow & 7)) << 4));
            }
            #pragma unroll
            for (int p = 0; p < 2; p++) {       // Bh then Bl
                uint32_t bBase = sS + (p ? SBL_OFF : SBH_OFF);
                uint32_t b[8][2];
                #pragma unroll
                for (int np = 0; np < 4; np++) {
                    int brow = warp_n * 64 + np * 16 + (mi >> 1) * 8 + r8;
                    int bc   = ks * 2 + (mi & 1);
                    uint32_t r[4];
                    ldsm_x4(r, bBase + brow * 128 + ((bc ^ (brow & 7)) << 4));
                    b[np * 2][0]     = r[0]; b[np * 2][1]     = r[1];
                    b[np * 2 + 1][0] = r[2]; b[np * 2 + 1][1] = r[3];
                }
                #pragma unroll
                for (int mt = 0; mt < 2; mt++)
                    #pragma unroll
                    for (int nt = 0; nt < 8; nt++)
                        mma_f16(acc[mt][nt], a[mt], b[nt]);
            }
        }
        __syncthreads();
    }

    int row0 = tileRow + warp_m * 32 + (lane >> 2);
    int col0 = warp_n * 64 + (lane & 3) * 2;
    #pragma unroll
    for (int mt = 0; mt < 2; mt++) {
        int r = row0 + mt * 16;
        #pragma unroll
        for (int nt = 0; nt < 8; nt++) {
            int cc = col0 + nt * 8;
            if (r < N_NODES)
                *(__half2*)&g_Whh[(size_t)r * OUT_F + cc] =
                    __floats2half2_rn(acc[mt][nt][0], acc[mt][nt][1]);
            if (r + 8 < N_NODES)
                *(__half2*)&g_Whh[(size_t)(r + 8) * OUT_F + cc] =
                    __floats2half2_rn(acc[mt][nt][2], acc[mt][nt][3]);
        }
    }
}

// ---------------- dtype detection + CSR side branch ---------------------------
__global__ void detect_kernel(const int* __restrict__ ei) {
    __shared__ int any;
    if (threadIdx.x == 0) any = 0;
    __syncthreads();
    for (int i = threadIdx.x; i < 2048; i += blockDim.x)
        if (ei[2 * i + 1] != 0) any = 1;
    __syncthreads();
    if (threadIdx.x == 0) g_is64 = any ? 0 : 1;
}

__global__ void init_cnt_kernel() {
    int i = blockIdx.x * blockDim.x + threadIdx.x;
    if (i < N_NODES) g_cnt[i] = 0;
}

__device__ __forceinline__ void load_edge(const void* ei, int e, int& s, int& d) {
    if (g_is64) {
        const long long* p = (const long long*)ei;
        s = (int)p[e];
        d = (int)p[NUM_E + e];
    } else {
        const int* p = (const int*)ei;
        s = p[e];
        d = p[NUM_E + e];
    }
}

__global__ __launch_bounds__(256) void hist_kernel(const void* __restrict__ ei) {
    int e = blockIdx.x * blockDim.x + threadIdx.x;
    if (e >= NUM_E) return;
    int s, d;
    load_edge(ei, e, s, d);
    atomicAdd(&g_cnt[s], 1);
}

__global__ __launch_bounds__(256) void scan_reduce_kernel() {
    __shared__ int ws[8];
    int tid = threadIdx.x, lane = tid & 31, wid = tid >> 5;
    int s = 0;
    #pragma unroll
    for (int j = 0; j < 4; j++) {
        int i = blockIdx.x * 1024 + j * 256 + tid;
        if (i < N_NODES) s += g_cnt[i];
    }
    #pragma unroll
    for (int o = 16; o; o >>= 1) s += __shfl_xor_sync(0xFFFFFFFFu, s, o);
    if (lane == 0) ws[wid] = s;
    __syncthreads();
    if (tid == 0) {
        int t = 0;
        #pragma unroll
        for (int w = 0; w < 8; w++) t += ws[w];
        g_bsum[blockIdx.x] = t;
    }
}

__global__ void scan_mid_kernel() {
    __shared__ int w0sum;
    int t = threadIdx.x;            // 64 threads
    int lane = t & 31, w = t >> 5;
    const int NBLK = (N_NODES + 1023) / 1024;   // 49
    int v = (t < NBLK) ? g_bsum[t] : 0;
    int x = v;
    #pragma unroll
    for (int o = 1; o < 32; o <<= 1) {
        int y = __shfl_up_sync(0xFFFFFFFFu, x, o);
        if (lane >= o) x += y;
    }
    if (w == 0 && lane == 31) w0sum = x;
    __syncthreads();
    int incl = x + (w == 1 ? w0sum : 0);
    if (t < NBLK) g_boff[t] = incl - v;   // exclusive
}

__global__ __launch_bounds__(1024) void scan_final_kernel() {
    __shared__ int warpsum[32];
    int tid = threadIdx.x, lane = tid & 31, wid = tid >> 5;
    int i = blockIdx.x * 1024 + tid;
    int v = (i < N_NODES) ? g_cnt[i] : 0;
    int x = v;
    #pragma unroll
    for (int o = 1; o < 32; o <<= 1) {
        int y = __shfl_up_sync(0xFFFFFFFFu, x, o);
        if (lane >= o) x += y;
    }
    if (lane == 31) warpsum[wid] = x;
    __syncthreads();
    if (wid == 0) {
        int s = warpsum[lane];
        #pragma unroll
        for (int o = 1; o < 32; o <<= 1) {
            int y = __shfl_up_sync(0xFFFFFFFFu, s, o);
            if (lane >= o) s += y;
        }
        warpsum[lane] = s;
    }
    __syncthreads();
    int base = (wid > 0) ? warpsum[wid - 1] : 0;
    int excl = g_boff[blockIdx.x] + base + x - v;
    if (i < N_NODES) {
        g_off[i]    = excl;
        g_cursor[i] = excl;
    }
    if (blockIdx.x == 0 && tid == 0) g_off[N_NODES] = NUM_E;
}

// fill: packed CSR record (dst, bits(exp(logit)))
__global__ __launch_bounds__(256) void fill_kernel(const void* __restrict__ ei) {
    int e = blockIdx.x * blockDim.x + threadIdx.x;
    if (e >= NUM_E) return;
    int s, d;
    load_edge(ei, e, s, d);
    float lg  = leaky_logit(__ldg(&g_s1[s]) + __ldg(&g_s2[d]));
    int   pos = atomicAdd(&g_cursor[s], 1);
    g_csr[pos] = make_uint2((unsigned)d, __float_as_uint(__expf(lg)));
}

// ---------------- aggregate: warp per node, 8-lane group per edge -------------
// lane = g*8 + l8; lane covers feats [l8*16, l8*16+16) = 32B (2x LDG.128);
// groups 0..3 take edge slots 4j+g -> 4 edges in flight, chain 8 per batch.
__global__ __launch_bounds__(256) void agg_kernel(float* __restrict__ out) {
    int src  = blockIdx.x * 8 + (threadIdx.x >> 5);
    if (src >= N_NODES) return;
    int lane = threadIdx.x & 31;
    int l8   = lane & 7;
    int g    = lane >> 3;
    int beg  = g_off[src];
    int end  = g_off[src + 1];

    float4* out4 = (float4*)out;
    if (beg == end) {
        if (lane < 8) {
            #pragma unroll
            for (int k = 0; k < 4; k++)
                out4[(size_t)src * 32 + l8 * 4 + k] = make_float4(0.f, 0.f, 0.f, 0.f);
        }
        return;
    }

    float acc[16];
    #pragma unroll
    for (int i = 0; i < 16; i++) acc[i] = 0.0f;
    float den = 0.f;

    for (int base = beg; base < end; base += 32) {
        int  idx   = base + lane;
        bool valid = idx < end;
        uint2 rec = valid ? __ldg(&g_csr[idx]) : make_uint2(0u, 0u);
        int   dn  = (int)rec.x;
        float w   = valid ? __uint_as_float(rec.y) : 0.0f;
        den += w;
        int cnt = min(end - base, 32);
        #pragma unroll
        for (int j = 0; j < 8; j++) {
            int   sl = j * 4 + g;
            int   dj = __shfl_sync(0xFFFFFFFFu, dn, sl);
            float wj = __shfl_sync(0xFFFFFFFFu, w,  sl);
            if (sl < cnt) {
                const uint4* p = (const uint4*)&g_Whh[(size_t)dj * OUT_F + l8 * 16];
                uint4 u0 = __ldg(p);
                uint4 u1 = __ldg(p + 1);
                float2 f;
                f = __half22float2(*(__half2*)&u0.x); acc[0] += wj * f.x; acc[1] += wj * f.y;
                f = __half22float2(*(__half2*)&u0.y); acc[2] += wj * f.x; acc[3] += wj * f.y;
                f = __half22float2(*(__half2*)&u0.z); acc[4] += wj * f.x; acc[5] += wj * f.y;
                f = __half22float2(*(__half2*)&u0.w); acc[6] += wj * f.x; acc[7] += wj * f.y;
                f = __half22float2(*(__half2*)&u1.x); acc[8] += wj * f.x; acc[9] += wj * f.y;
                f = __half22float2(*(__half2*)&u1.y); acc[10] += wj * f.x; acc[11] += wj * f.y;
                f = __half22float2(*(__half2*)&u1.z); acc[12] += wj * f.x; acc[13] += wj * f.y;
                f = __half22float2(*(__half2*)&u1.w); acc[14] += wj * f.x; acc[15] += wj * f.y;
            }
        }
    }

    // combine the 4 groups (same features, disjoint edge subsets)
    #pragma unroll
    for (int i = 0; i < 16; i++) {
        acc[i] += __shfl_xor_sync(0xFFFFFFFFu, acc[i], 8);
        acc[i] += __shfl_xor_sync(0xFFFFFFFFu, acc[i], 16);
    }
    #pragma unroll
    for (int o = 16; o; o >>= 1)
        den += __shfl_xor_sync(0xFFFFFFFFu, den, o);
    float inv = (den > 0.0f) ? (1.0f / den) : 0.0f;

    if (lane < 8) {
        #pragma unroll
        for (int k = 0; k < 4; k++) {
            float4 r;
            r.x = fmaxf(acc[4 * k + 0] * inv, 0.0f);
            r.y = fmaxf(acc[4 * k + 1] * inv, 0.0f);
            r.z = fmaxf(acc[4 * k + 2] * inv, 0.0f);
            r.w = fmaxf(acc[4 * k + 3] * inv, 0.0f);
            out4[(size_t)src * 32 + l8 * 4 + k] = r;
        }
    }
}

// ---------------- launch ------------------------------------------------------
extern "C" void kernel_launch(void* const* d_in, const int* in_sizes, int n_in,
                              void* d_out, int out_size) {
    const float* h  = (const float*)d_in[0];
    const float* W  = (const float*)d_in[1];
    const float* a  = (const float*)d_in[2];
    const void*  ei = d_in[3];
    float* out = (float*)d_out;

    static cudaStream_t s2 = nullptr;
    static cudaEvent_t evFork = nullptr, evJoin = nullptr, evMv = nullptr;
    if (s2 == nullptr) {
        cudaStreamCreateWithFlags(&s2, cudaStreamNonBlocking);
        cudaEventCreateWithFlags(&evFork, cudaEventDisableTiming);
        cudaEventCreateWithFlags(&evJoin, cudaEventDisableTiming);
        cudaEventCreateWithFlags(&evMv, cudaEventDisableTiming);
        cudaFuncSetAttribute(gemm_f16_kernel,
                             cudaFuncAttributeMaxDynamicSharedMemorySize, GEMM_SMEM);
    }

    const int NBLK = (N_NODES + 1023) / 1024;   // 49

    cudaEventRecord(evFork, 0);
    cudaStreamWaitEvent(s2, evFork, 0);

    // s2: CSR build (edge_index only)
    detect_kernel<<<1, 256, 0, s2>>>((const int*)ei);
    init_cnt_kernel<<<(N_NODES + 255) / 256, 256, 0, s2>>>();
    hist_kernel<<<(NUM_E + 255) / 256, 256, 0, s2>>>(ei);
    scan_reduce_kernel<<<NBLK, 256, 0, s2>>>();
    scan_mid_kernel<<<1, 64, 0, s2>>>();
    scan_final_kernel<<<NBLK, 1024, 0, s2>>>();

    // main: u -> fused convert+matvec -> convert_w -> gemm
    u_kernel<<<(IN_F + 7) / 8, 256>>>(W, a);
    convmv_kernel<<<(PAD_ROWS + 7) / 8, 256>>>(h);
    cudaEventRecord(evMv, 0);   // s1/s2 + A16 ready
    convert_w_kernel<<<(OUT_F * (IN_F / 8) + 255) / 256, 256>>>(W);
    gemm_f16_kernel<<<N_TILES, 256, GEMM_SMEM>>>();

    // s2: fill once s1/s2 ready (overlaps gemm)
    cudaStreamWaitEvent(s2, evMv, 0);
    fill_kernel<<<(NUM_E + 255) / 256, 256, 0, s2>>>(ei);
    cudaEventRecord(evJoin, s2);

    // join, then aggregate
    cudaStreamWaitEvent(0, evJoin, 0);
    agg_kernel<<<(N_NODES + 7) / 8, 256>>>(out);
}

// round 12
// speedup vs baseline: 1.1443x; 1.0458x over previous
#include <cuda_runtime.h>
#include <cuda_fp16.h>
#include <cstdint>

#define N_NODES 50000
#define NUM_E   1600000
#define IN_F    512
#define OUT_F   128
#define NEG_SLOPE 0.01f
#define INV_T     2.0f   // 1 / TEMPERATURE (0.5)

#define TILE_M   128
#define N_TILES  391                   // ceil(50000/128)
#define PAD_ROWS (N_TILES * TILE_M)    // 50048
#define GBK      64                    // K per chunk
#define NCHUNK   (IN_F / GBK)          // 8

// smem: stage = [ A 16K | Bh 16K | Bl 16K ] fp16 swizzled; double buffered
#define SBH_OFF     16384
#define SBL_OFF     32768
#define STAGE_BYTES 49152
#define GEMM_SMEM   (2 * STAGE_BYTES)  // 96 KB -> 2 CTAs/SM

// ---------------- scratch (static device globals; no allocations) -----------
__device__ __half   g_Whh[(size_t)N_NODES * OUT_F];     // 12.8 MB (fp16 Wh)
__device__ __half   g_A16[(size_t)PAD_ROWS * IN_F];     // 51.2 MB (fp16 h)
__device__ __half   g_Bh16[(size_t)OUT_F * IN_F];       // 128 KB (B^T hi fp16)
__device__ __half   g_Bl16[(size_t)OUT_F * IN_F];       // 128 KB (B^T lo fp16)
__device__ float    g_u1[IN_F];
__device__ float    g_u2[IN_F];
__device__ float    g_s1[N_NODES];
__device__ float    g_s2[N_NODES];
__device__ int      g_cnt[N_NODES];
__device__ int      g_off[N_NODES + 1];
__device__ int      g_cursor[N_NODES];
__device__ int      g_csr_dst[NUM_E];                   // dst only (w computed in agg)
__device__ int      g_bsum[64];
__device__ int      g_boff[64];
__device__ int      g_is64;

// ---------------- helpers ----------------------------------------------------
__device__ __forceinline__ uint32_t smem_u32(const void* p) {
    uint32_t a;
    asm("{ .reg .u64 t; cvta.to.shared.u64 t, %1; cvt.u32.u64 %0, t; }" : "=r"(a) : "l"(p));
    return a;
}
__device__ __forceinline__ void cp_async16(uint32_t dst, const void* src) {
    asm volatile("cp.async.cg.shared.global [%0], [%1], 16;"
                 :: "r"(dst), "l"(__cvta_generic_to_global(src)) : "memory");
}
#define CP_COMMIT() asm volatile("cp.async.commit_group;" ::: "memory")
#define CP_WAIT1()  asm volatile("cp.async.wait_group 1;" ::: "memory")

__device__ __forceinline__ void ldsm_x4(uint32_t* r, uint32_t addr) {
    asm volatile("ldmatrix.sync.aligned.m8n8.x4.shared.b16 {%0,%1,%2,%3}, [%4];"
                 : "=r"(r[0]), "=r"(r[1]), "=r"(r[2]), "=r"(r[3]) : "r"(addr));
}
__device__ __forceinline__ void mma_f16(float* d, const uint32_t* a, const uint32_t* b) {
    asm volatile("mma.sync.aligned.m16n8k16.row.col.f32.f16.f16.f32 "
                 "{%0,%1,%2,%3}, {%4,%5,%6,%7}, {%8,%9}, {%0,%1,%2,%3};"
                 : "+f"(d[0]), "+f"(d[1]), "+f"(d[2]), "+f"(d[3])
                 : "r"(a[0]), "r"(a[1]), "r"(a[2]), "r"(a[3]), "r"(b[0]), "r"(b[1]));
}

__device__ __forceinline__ float leaky_logit(float v) {
    v = (v >= 0.0f) ? v : NEG_SLOPE * v;
    return v * INV_T;
}

// ---------------- u1 = W @ a1, u2 = W @ a2 (warp per k row) -------------------
__global__ __launch_bounds__(256) void u_kernel(const float* __restrict__ W,
                                                const float* __restrict__ a) {
    int k    = blockIdx.x * 8 + (threadIdx.x >> 5);
    int lane = threadIdx.x & 31;
    if (k >= IN_F) return;
    float4 w  = *(const float4*)&W[(size_t)k * OUT_F + lane * 4];
    float4 a1 = *(const float4*)&a[lane * 4];
    float4 a2 = *(const float4*)&a[OUT_F + lane * 4];
    float p1 = w.x * a1.x + w.y * a1.y + w.z * a1.z + w.w * a1.w;
    float p2 = w.x * a2.x + w.y * a2.y + w.z * a2.z + w.w * a2.w;
    #pragma unroll
    for (int o = 16; o; o >>= 1) {
        p1 += __shfl_down_sync(0xFFFFFFFFu, p1, o);
        p2 += __shfl_down_sync(0xFFFFFFFFu, p2, o);
    }
    if (lane == 0) { g_u1[k] = p1; g_u2[k] = p2; }
}

// ---------------- fused: h -> fp16 A16  AND  s1/s2 = h@u1, h@u2 ---------------
__global__ __launch_bounds__(256) void convmv_kernel(const float* __restrict__ h) {
    __shared__ float su1[IN_F], su2[IN_F];
    int tid = threadIdx.x;
    if (tid < IN_F / 2) {
        ((float2*)su1)[tid] = ((const float2*)g_u1)[tid];
        ((float2*)su2)[tid] = ((const float2*)g_u2)[tid];
    }
    __syncthreads();
    int row  = blockIdx.x * 8 + (tid >> 5);
    int lane = tid & 31;
    if (row >= PAD_ROWS) return;

    if (row >= N_NODES) {   // zero padded rows
        #pragma unroll
        for (int i = 0; i < 4; i++)
            *(uint2*)&g_A16[(size_t)row * IN_F + i * 128 + lane * 4] = make_uint2(0, 0);
        return;
    }

    float p1 = 0.f, p2 = 0.f;
    #pragma unroll
    for (int i = 0; i < 4; i++) {
        int col = i * 128 + lane * 4;
        float4 v  = __ldg((const float4*)&h[(size_t)row * IN_F + col]);
        float4 q1 = *(const float4*)&su1[col];
        float4 q2 = *(const float4*)&su2[col];
        p1 += v.x * q1.x + v.y * q1.y + v.z * q1.z + v.w * q1.w;
        p2 += v.x * q2.x + v.y * q2.y + v.z * q2.z + v.w * q2.w;
        __half2 h0 = __floats2half2_rn(v.x, v.y);
        __half2 h1 = __floats2half2_rn(v.z, v.w);
        uint2 q; q.x = *(uint32_t*)&h0; q.y = *(uint32_t*)&h1;
        *(uint2*)&g_A16[(size_t)row * IN_F + col] = q;
    }
    #pragma unroll
    for (int o = 16; o; o >>= 1) {
        p1 += __shfl_down_sync(0xFFFFFFFFu, p1, o);
        p2 += __shfl_down_sync(0xFFFFFFFFu, p2, o);
    }
    if (lane == 0) { g_s1[row] = p1; g_s2[row] = p2; }
}

// ---------------- W -> B^T fp16 hi/lo split ------------------------------------
__global__ __launch_bounds__(256) void convert_w_kernel(const float* __restrict__ W) {
    int idx = blockIdx.x * 256 + threadIdx.x;
    if (idx >= OUT_F * (IN_F / 8)) return;
    int n  = idx / (IN_F / 8);
    int k8 = (idx % (IN_F / 8)) * 8;
    unsigned short hb[8], lb[8];
    #pragma unroll
    for (int j = 0; j < 8; j++) {
        float v = W[(size_t)(k8 + j) * OUT_F + n];
        __half hv = __float2half_rn(v);
        __half lv = __float2half_rn(v - __half2float(hv));
        hb[j] = *(unsigned short*)&hv;
        lb[j] = *(unsigned short*)&lv;
    }
    uint4 qh, ql;
    qh.x = hb[0] | ((uint32_t)hb[1] << 16); qh.y = hb[2] | ((uint32_t)hb[3] << 16);
    qh.z = hb[4] | ((uint32_t)hb[5] << 16); qh.w = hb[6] | ((uint32_t)hb[7] << 16);
    ql.x = lb[0] | ((uint32_t)lb[1] << 16); ql.y = lb[2] | ((uint32_t)lb[3] << 16);
    ql.z = lb[4] | ((uint32_t)lb[5] << 16); ql.w = lb[6] | ((uint32_t)lb[7] << 16);
    size_t off = (size_t)n * IN_F + k8;
    *(uint4*)&g_Bh16[off] = qh;
    *(uint4*)&g_Bl16[off] = ql;
}

// ---------------- GEMM: Wh(fp16) = A16 @ (Bh + Bl) ----------------------------
__global__ __launch_bounds__(256, 2) void gemm_f16_kernel() {
    extern __shared__ char smx[];
    const int tid  = threadIdx.x;
    const int lane = tid & 31, wid = tid >> 5;
    const int warp_m = wid & 3, warp_n = wid >> 2;   // 4 x 2 warp grid
    const int tileRow = blockIdx.x * TILE_M;
    const uint32_t sbase = smem_u32(smx);

    float acc[2][8][4];
    #pragma unroll
    for (int mt = 0; mt < 2; mt++)
        #pragma unroll
        for (int nt = 0; nt < 8; nt++)
            #pragma unroll
            for (int q = 0; q < 4; q++) acc[mt][nt][q] = 0.0f;

    auto load_stage = [&](int stage, int c) {
        int k0 = c * GBK;
        uint32_t sS = sbase + stage * STAGE_BYTES;
        #pragma unroll
        for (int i = 0; i < 4; i++) {
            int cid = tid + i * 256;            // 0..1023
            int row = cid >> 3, cc = cid & 7;
            uint32_t sw = (uint32_t)((cc ^ (row & 7)) << 4);
            cp_async16(sS + row * 128 + sw,
                       g_A16 + (size_t)(tileRow + row) * IN_F + k0 + cc * 8);
            cp_async16(sS + SBH_OFF + row * 128 + sw,
                       g_Bh16 + (size_t)row * IN_F + k0 + cc * 8);
            cp_async16(sS + SBL_OFF + row * 128 + sw,
                       g_Bl16 + (size_t)row * IN_F + k0 + cc * 8);
        }
    };

    load_stage(0, 0);
    CP_COMMIT();

    const int mi = lane >> 3, r8 = lane & 7;

    for (int c = 0; c < NCHUNK; c++) {
        if (c + 1 < NCHUNK) load_stage((c + 1) & 1, c + 1);
        CP_COMMIT();
        CP_WAIT1();
        __syncthreads();

        uint32_t sS = sbase + (c & 1) * STAGE_BYTES;

        #pragma unroll
        for (int ks = 0; ks < 4; ks++) {
            uint32_t a[2][4];
            #pragma unroll
            for (int mt = 0; mt < 2; mt++) {
                int arow = warp_m * 32 + mt * 16 + r8 + (mi & 1) * 8;
                int ac   = ks * 2 + (mi >> 1);
                ldsm_x4(a[mt], sS + arow * 128 + ((ac ^ (arow & 7)) << 4));
            }
            #pragma unroll
            for (int p = 0; p < 2; p++) {       // Bh then Bl
                uint32_t bBase = sS + (p ? SBL_OFF : SBH_OFF);
                uint32_t b[8][2];
                #pragma unroll
                for (int np = 0; np < 4; np++) {
                    int brow = warp_n * 64 + np * 16 + (mi >> 1) * 8 + r8;
                    int bc   = ks * 2 + (mi & 1);
                    uint32_t r[4];
                    ldsm_x4(r, bBase + brow * 128 + ((bc ^ (brow & 7)) << 4));
                    b[np * 2][0]     = r[0]; b[np * 2][1]     = r[1];
                    b[np * 2 + 1][0] = r[2]; b[np * 2 + 1][1] = r[3];
                }
                #pragma unroll
                for (int mt = 0; mt < 2; mt++)
                    #pragma unroll
                    for (int nt = 0; nt < 8; nt++)
                        mma_f16(acc[mt][nt], a[mt], b[nt]);
            }
        }
        __syncthreads();
    }

    int row0 = tileRow + warp_m * 32 + (lane >> 2);
    int col0 = warp_n * 64 + (lane & 3) * 2;
    #pragma unroll
    for (int mt = 0; mt < 2; mt++) {
        int r = row0 + mt * 16;
        #pragma unroll
        for (int nt = 0; nt < 8; nt++) {
            int cc = col0 + nt * 8;
            if (r < N_NODES)
                *(__half2*)&g_Whh[(size_t)r * OUT_F + cc] =
                    __floats2half2_rn(acc[mt][nt][0], acc[mt][nt][1]);
            if (r + 8 < N_NODES)
                *(__half2*)&g_Whh[(size_t)(r + 8) * OUT_F + cc] =
                    __floats2half2_rn(acc[mt][nt][2], acc[mt][nt][3]);
        }
    }
}

// ---------------- dtype detection + CSR side branch ---------------------------
__global__ void detect_kernel(const int* __restrict__ ei) {
    __shared__ int any;
    if (threadIdx.x == 0) any = 0;
    __syncthreads();
    for (int i = threadIdx.x; i < 2048; i += blockDim.x)
        if (ei[2 * i + 1] != 0) any = 1;
    __syncthreads();
    if (threadIdx.x == 0) g_is64 = any ? 0 : 1;
}

__global__ void init_cnt_kernel() {
    int i = blockIdx.x * blockDim.x + threadIdx.x;
    if (i < N_NODES) g_cnt[i] = 0;
}

__device__ __forceinline__ void load_edge(const void* ei, int e, int& s, int& d) {
    if (g_is64) {
        const long long* p = (const long long*)ei;
        s = (int)p[e];
        d = (int)p[NUM_E + e];
    } else {
        const int* p = (const int*)ei;
        s = p[e];
        d = p[NUM_E + e];
    }
}

__global__ __launch_bounds__(256) void hist_kernel(const void* __restrict__ ei) {
    int e = blockIdx.x * blockDim.x + threadIdx.x;
    if (e >= NUM_E) return;
    int s, d;
    load_edge(ei, e, s, d);
    atomicAdd(&g_cnt[s], 1);
}

__global__ __launch_bounds__(256) void scan_reduce_kernel() {
    __shared__ int ws[8];
    int tid = threadIdx.x, lane = tid & 31, wid = tid >> 5;
    int s = 0;
    #pragma unroll
    for (int j = 0; j < 4; j++) {
        int i = blockIdx.x * 1024 + j * 256 + tid;
        if (i < N_NODES) s += g_cnt[i];
    }
    #pragma unroll
    for (int o = 16; o; o >>= 1) s += __shfl_xor_sync(0xFFFFFFFFu, s, o);
    if (lane == 0) ws[wid] = s;
    __syncthreads();
    if (tid == 0) {
        int t = 0;
        #pragma unroll
        for (int w = 0; w < 8; w++) t += ws[w];
        g_bsum[blockIdx.x] = t;
    }
}

__global__ void scan_mid_kernel() {
    __shared__ int w0sum;
    int t = threadIdx.x;            // 64 threads
    int lane = t & 31, w = t >> 5;
    const int NBLK = (N_NODES + 1023) / 1024;   // 49
    int v = (t < NBLK) ? g_bsum[t] : 0;
    int x = v;
    #pragma unroll
    for (int o = 1; o < 32; o <<= 1) {
        int y = __shfl_up_sync(0xFFFFFFFFu, x, o);
        if (lane >= o) x += y;
    }
    if (w == 0 && lane == 31) w0sum = x;
    __syncthreads();
    int incl = x + (w == 1 ? w0sum : 0);
    if (t < NBLK) g_boff[t] = incl - v;   // exclusive
}

__global__ __launch_bounds__(1024) void scan_final_kernel() {
    __shared__ int warpsum[32];
    int tid = threadIdx.x, lane = tid & 31, wid = tid >> 5;
    int i = blockIdx.x * 1024 + tid;
    int v = (i < N_NODES) ? g_cnt[i] : 0;
    int x = v;
    #pragma unroll
    for (int o = 1; o < 32; o <<= 1) {
        int y = __shfl_up_sync(0xFFFFFFFFu, x, o);
        if (lane >= o) x += y;
    }
    if (lane == 31) warpsum[wid] = x;
    __syncthreads();
    if (wid == 0) {
        int s = warpsum[lane];
        #pragma unroll
        for (int o = 1; o < 32; o <<= 1) {
            int y = __shfl_up_sync(0xFFFFFFFFu, s, o);
            if (lane >= o) s += y;
        }
        warpsum[lane] = s;
    }
    __syncthreads();
    int base = (wid > 0) ? warpsum[wid - 1] : 0;
    int excl = g_boff[blockIdx.x] + base + x - v;
    if (i < N_NODES) {
        g_off[i]    = excl;
        g_cursor[i] = excl;
    }
    if (blockIdx.x == 0 && tid == 0) g_off[N_NODES] = NUM_E;
}

// fill: dst only — independent of s1/s2, runs fully in the side branch
__global__ __launch_bounds__(256) void fill_kernel(const void* __restrict__ ei) {
    int e = blockIdx.x * blockDim.x + threadIdx.x;
    if (e >= NUM_E) return;
    int s, d;
    load_edge(ei, e, s, d);
    int pos = atomicAdd(&g_cursor[s], 1);
    g_csr_dst[pos] = d;
}

// ---------------- aggregate: warp per node, half-warp per edge ----------------
// w computed inline: exp(leaky(s1[src] + s2[dst]) * 2)
__global__ __launch_bounds__(256) void agg_kernel(float* __restrict__ out) {
    int src  = blockIdx.x * 8 + (threadIdx.x >> 5);
    if (src >= N_NODES) return;
    int lane = threadIdx.x & 31;
    int l16  = lane & 15;
    int half = (lane >> 4) & 1;
    int beg  = g_off[src];
    int end  = g_off[src + 1];

    float4* out4 = (float4*)out;
    if (beg == end) {
        if (lane < 16) {
            out4[(size_t)src * 32 + l16 * 2]     = make_float4(0.f, 0.f, 0.f, 0.f);
            out4[(size_t)src * 32 + l16 * 2 + 1] = make_float4(0.f, 0.f, 0.f, 0.f);
        }
        return;
    }

    const float s1s = __ldg(&g_s1[src]);

    float acc[8];
    #pragma unroll
    for (int i = 0; i < 8; i++) acc[i] = 0.0f;
    float den = 0.f;

    for (int base = beg; base < end; base += 32) {
        int  idx   = base + lane;
        bool valid = idx < end;
        int   dn = valid ? __ldg(&g_csr_dst[idx]) : 0;
        float w  = 0.0f;
        if (valid)
            w = __expf(leaky_logit(s1s + __ldg(&g_s2[dn])));
        den += w;
        int cnt   = min(end - base, 32);
        int iters = (cnt + 1) >> 1;
        #pragma unroll 4
        for (int j = 0; j < iters; j++) {
            int   sl = 2 * j + half;
            int   dj = __shfl_sync(0xFFFFFFFFu, dn, sl);
            float wj = __shfl_sync(0xFFFFFFFFu, w,  sl);
            uint4 u = __ldg((const uint4*)&g_Whh[(size_t)dj * OUT_F + l16 * 8]);
            float2 f0 = __half22float2(*(__half2*)&u.x);
            float2 f1 = __half22float2(*(__half2*)&u.y);
            float2 f2 = __half22float2(*(__half2*)&u.z);
            float2 f3 = __half22float2(*(__half2*)&u.w);
            acc[0] += wj * f0.x; acc[1] += wj * f0.y;
            acc[2] += wj * f1.x; acc[3] += wj * f1.y;
            acc[4] += wj * f2.x; acc[5] += wj * f2.y;
            acc[6] += wj * f3.x; acc[7] += wj * f3.y;
        }
    }

    // combine halves (same features, disjoint edge subsets)
    #pragma unroll
    for (int i = 0; i < 8; i++)
        acc[i] += __shfl_xor_sync(0xFFFFFFFFu, acc[i], 16);
    #pragma unroll
    for (int o = 16; o; o >>= 1)
        den += __shfl_xor_sync(0xFFFFFFFFu, den, o);
    float inv = (den > 0.0f) ? (1.0f / den) : 0.0f;

    if (lane < 16) {
        float4 r0, r1;
        r0.x = fmaxf(acc[0] * inv, 0.0f); r0.y = fmaxf(acc[1] * inv, 0.0f);
        r0.z = fmaxf(acc[2] * inv, 0.0f); r0.w = fmaxf(acc[3] * inv, 0.0f);
        r1.x = fmaxf(acc[4] * inv, 0.0f); r1.y = fmaxf(acc[5] * inv, 0.0f);
        r1.z = fmaxf(acc[6] * inv, 0.0f); r1.w = fmaxf(acc[7] * inv, 0.0f);
        out4[(size_t)src * 32 + l16 * 2]     = r0;
        out4[(size_t)src * 32 + l16 * 2 + 1] = r1;
    }
}

// ---------------- launch ------------------------------------------------------
extern "C" void kernel_launch(void* const* d_in, const int* in_sizes, int n_in,
                              void* d_out, int out_size) {
    const float* h  = (const float*)d_in[0];
    const float* W  = (const float*)d_in[1];
    const float* a  = (const float*)d_in[2];
    const void*  ei = d_in[3];
    float* out = (float*)d_out;

    static cudaStream_t s2 = nullptr;
    static cudaEvent_t evFork = nullptr, evJoin = nullptr;
    if (s2 == nullptr) {
        cudaStreamCreateWithFlags(&s2, cudaStreamNonBlocking);
        cudaEventCreateWithFlags(&evFork, cudaEventDisableTiming);
        cudaEventCreateWithFlags(&evJoin, cudaEventDisableTiming);
        cudaFuncSetAttribute(gemm_f16_kernel,
                             cudaFuncAttributeMaxDynamicSharedMemorySize, GEMM_SMEM);
    }

    const int NBLK = (N_NODES + 1023) / 1024;   // 49

    cudaEventRecord(evFork, 0);
    cudaStreamWaitEvent(s2, evFork, 0);

    // s2: full CSR build incl. fill (depends only on edge_index)
    detect_kernel<<<1, 256, 0, s2>>>((const int*)ei);
    init_cnt_kernel<<<(N_NODES + 255) / 256, 256, 0, s2>>>();
    hist_kernel<<<(NUM_E + 255) / 256, 256, 0, s2>>>(ei);
    scan_reduce_kernel<<<NBLK, 256, 0, s2>>>();
    scan_mid_kernel<<<1, 64, 0, s2>>>();
    scan_final_kernel<<<NBLK, 1024, 0, s2>>>();
    fill_kernel<<<(NUM_E + 255) / 256, 256, 0, s2>>>(ei);
    cudaEventRecord(evJoin, s2);

    // main: u -> fused convert+matvec -> convert_w -> gemm
    u_kernel<<<(IN_F + 7) / 8, 256>>>(W, a);
    convmv_kernel<<<(PAD_ROWS + 7) / 8, 256>>>(h);
    convert_w_kernel<<<(OUT_F * (IN_F / 8) + 255) / 256, 256>>>(W);
    gemm_f16_kernel<<<N_TILES, 256, GEMM_SMEM>>>();

    // join, then aggregate (needs s1/s2 + Whh from main, CSR from s2)
    cudaStreamWaitEvent(0, evJoin, 0);
    agg_kernel<<<(N_NODES + 7) / 8, 256>>>(out);
}

// round 13
// speedup vs baseline: 1.2378x; 1.0817x over previous
#include <cuda_runtime.h>
#include <cuda_fp16.h>
#include <cstdint>

#define N_NODES 50000
#define NUM_E   1600000
#define IN_F    512
#define OUT_F   128
#define NEG_SLOPE 0.01f
#define INV_T     2.0f   // 1 / TEMPERATURE (0.5)

#define TILE_M   128
#define N_TILES  391                   // ceil(50000/128)
#define PAD_ROWS (N_TILES * TILE_M)    // 50048
#define GBK      64                    // K per chunk
#define NCHUNK   (IN_F / GBK)          // 8

// smem: stage = [ A 16K | B 16K ] fp16 swizzled; double buffered
#define SB_OFF      16384
#define STAGE_BYTES 32768
#define GEMM_SMEM   (2 * STAGE_BYTES)  // 64 KB -> 2+ CTAs/SM

// ---------------- scratch (static device globals; no allocations) -----------
__device__ __half   g_Whh[(size_t)N_NODES * OUT_F];     // 12.8 MB (fp16 Wh)
__device__ __half   g_A16[(size_t)PAD_ROWS * IN_F];     // 51.2 MB (fp16 h)
__device__ __half   g_B16[(size_t)OUT_F * IN_F];        // 128 KB (B^T fp16)
__device__ float    g_u1[IN_F];
__device__ float    g_u2[IN_F];
__device__ float    g_s1[N_NODES];
__device__ float    g_s2[N_NODES];
__device__ int      g_cnt[N_NODES];
__device__ int      g_off[N_NODES + 1];
__device__ int      g_cursor[N_NODES];
__device__ int      g_csr_dst[NUM_E];                   // dst only (w computed in agg)
__device__ int      g_bsum[64];
__device__ int      g_boff[64];
__device__ int      g_is64;

// ---------------- helpers ----------------------------------------------------
__device__ __forceinline__ uint32_t smem_u32(const void* p) {
    uint32_t a;
    asm("{ .reg .u64 t; cvta.to.shared.u64 t, %1; cvt.u32.u64 %0, t; }" : "=r"(a) : "l"(p));
    return a;
}
__device__ __forceinline__ void cp_async16(uint32_t dst, const void* src) {
    asm volatile("cp.async.cg.shared.global [%0], [%1], 16;"
                 :: "r"(dst), "l"(__cvta_generic_to_global(src)) : "memory");
}
#define CP_COMMIT() asm volatile("cp.async.commit_group;" ::: "memory")
#define CP_WAIT1()  asm volatile("cp.async.wait_group 1;" ::: "memory")

__device__ __forceinline__ void ldsm_x4(uint32_t* r, uint32_t addr) {
    asm volatile("ldmatrix.sync.aligned.m8n8.x4.shared.b16 {%0,%1,%2,%3}, [%4];"
                 : "=r"(r[0]), "=r"(r[1]), "=r"(r[2]), "=r"(r[3]) : "r"(addr));
}
__device__ __forceinline__ void mma_f16(float* d, const uint32_t* a, const uint32_t* b) {
    asm volatile("mma.sync.aligned.m16n8k16.row.col.f32.f16.f16.f32 "
                 "{%0,%1,%2,%3}, {%4,%5,%6,%7}, {%8,%9}, {%0,%1,%2,%3};"
                 : "+f"(d[0]), "+f"(d[1]), "+f"(d[2]), "+f"(d[3])
                 : "r"(a[0]), "r"(a[1]), "r"(a[2]), "r"(a[3]), "r"(b[0]), "r"(b[1]));
}

__device__ __forceinline__ float leaky_logit(float v) {
    v = (v >= 0.0f) ? v : NEG_SLOPE * v;
    return v * INV_T;
}

// ---------------- u1 = W @ a1, u2 = W @ a2 (warp per k row) -------------------
__global__ __launch_bounds__(256) void u_kernel(const float* __restrict__ W,
                                                const float* __restrict__ a) {
    int k    = blockIdx.x * 8 + (threadIdx.x >> 5);
    int lane = threadIdx.x & 31;
    if (k >= IN_F) return;
    float4 w  = *(const float4*)&W[(size_t)k * OUT_F + lane * 4];
    float4 a1 = *(const float4*)&a[lane * 4];
    float4 a2 = *(const float4*)&a[OUT_F + lane * 4];
    float p1 = w.x * a1.x + w.y * a1.y + w.z * a1.z + w.w * a1.w;
    float p2 = w.x * a2.x + w.y * a2.y + w.z * a2.z + w.w * a2.w;
    #pragma unroll
    for (int o = 16; o; o >>= 1) {
        p1 += __shfl_down_sync(0xFFFFFFFFu, p1, o);
        p2 += __shfl_down_sync(0xFFFFFFFFu, p2, o);
    }
    if (lane == 0) { g_u1[k] = p1; g_u2[k] = p2; }
}

// ---------------- fused: h -> fp16 A16  AND  s1/s2 = h@u1, h@u2 ---------------
__global__ __launch_bounds__(256) void convmv_kernel(const float* __restrict__ h) {
    __shared__ float su1[IN_F], su2[IN_F];
    int tid = threadIdx.x;
    if (tid < IN_F / 2) {
        ((float2*)su1)[tid] = ((const float2*)g_u1)[tid];
        ((float2*)su2)[tid] = ((const float2*)g_u2)[tid];
    }
    __syncthreads();
    int row  = blockIdx.x * 8 + (tid >> 5);
    int lane = tid & 31;
    if (row >= PAD_ROWS) return;

    if (row >= N_NODES) {   // zero padded rows
        #pragma unroll
        for (int i = 0; i < 4; i++)
            *(uint2*)&g_A16[(size_t)row * IN_F + i * 128 + lane * 4] = make_uint2(0, 0);
        return;
    }

    float p1 = 0.f, p2 = 0.f;
    #pragma unroll
    for (int i = 0; i < 4; i++) {
        int col = i * 128 + lane * 4;
        float4 v  = __ldg((const float4*)&h[(size_t)row * IN_F + col]);
        float4 q1 = *(const float4*)&su1[col];
        float4 q2 = *(const float4*)&su2[col];
        p1 += v.x * q1.x + v.y * q1.y + v.z * q1.z + v.w * q1.w;
        p2 += v.x * q2.x + v.y * q2.y + v.z * q2.z + v.w * q2.w;
        __half2 h0 = __floats2half2_rn(v.x, v.y);
        __half2 h1 = __floats2half2_rn(v.z, v.w);
        uint2 q; q.x = *(uint32_t*)&h0; q.y = *(uint32_t*)&h1;
        *(uint2*)&g_A16[(size_t)row * IN_F + col] = q;
    }
    #pragma unroll
    for (int o = 16; o; o >>= 1) {
        p1 += __shfl_down_sync(0xFFFFFFFFu, p1, o);
        p2 += __shfl_down_sync(0xFFFFFFFFu, p2, o);
    }
    if (lane == 0) { g_s1[row] = p1; g_s2[row] = p2; }
}

// ---------------- W -> B^T fp16 ------------------------------------------------
__global__ __launch_bounds__(256) void convert_w_kernel(const float* __restrict__ W) {
    int idx = blockIdx.x * 256 + threadIdx.x;
    if (idx >= OUT_F * (IN_F / 8)) return;
    int n  = idx / (IN_F / 8);
    int k8 = (idx % (IN_F / 8)) * 8;
    unsigned short hb[8];
    #pragma unroll
    for (int j = 0; j < 8; j++) {
        __half hv = __float2half_rn(W[(size_t)(k8 + j) * OUT_F + n]);
        hb[j] = *(unsigned short*)&hv;
    }
    uint4 qh;
    qh.x = hb[0] | ((uint32_t)hb[1] << 16); qh.y = hb[2] | ((uint32_t)hb[3] << 16);
    qh.z = hb[4] | ((uint32_t)hb[5] << 16); qh.w = hb[6] | ((uint32_t)hb[7] << 16);
    *(uint4*)&g_B16[(size_t)n * IN_F + k8] = qh;
}

// ---------------- GEMM: Wh(fp16) = A16 @ B16 (single pass) --------------------
__global__ __launch_bounds__(256, 2) void gemm_f16_kernel() {
    extern __shared__ char smx[];
    const int tid  = threadIdx.x;
    const int lane = tid & 31, wid = tid >> 5;
    const int warp_m = wid & 3, warp_n = wid >> 2;   // 4 x 2 warp grid
    const int tileRow = blockIdx.x * TILE_M;
    const uint32_t sbase = smem_u32(smx);

    float acc[2][8][4];
    #pragma unroll
    for (int mt = 0; mt < 2; mt++)
        #pragma unroll
        for (int nt = 0; nt < 8; nt++)
            #pragma unroll
            for (int q = 0; q < 4; q++) acc[mt][nt][q] = 0.0f;

    auto load_stage = [&](int stage, int c) {
        int k0 = c * GBK;
        uint32_t sS = sbase + stage * STAGE_BYTES;
        #pragma unroll
        for (int i = 0; i < 4; i++) {
            int cid = tid + i * 256;            // 0..1023
            int row = cid >> 3, cc = cid & 7;
            uint32_t sw = (uint32_t)((cc ^ (row & 7)) << 4);
            cp_async16(sS + row * 128 + sw,
                       g_A16 + (size_t)(tileRow + row) * IN_F + k0 + cc * 8);
            cp_async16(sS + SB_OFF + row * 128 + sw,
                       g_B16 + (size_t)row * IN_F + k0 + cc * 8);
        }
    };

    load_stage(0, 0);
    CP_COMMIT();

    const int mi = lane >> 3, r8 = lane & 7;

    for (int c = 0; c < NCHUNK; c++) {
        if (c + 1 < NCHUNK) load_stage((c + 1) & 1, c + 1);
        CP_COMMIT();
        CP_WAIT1();
        __syncthreads();

        uint32_t sS = sbase + (c & 1) * STAGE_BYTES;

        #pragma unroll
        for (int ks = 0; ks < 4; ks++) {
            uint32_t a[2][4];
            #pragma unroll
            for (int mt = 0; mt < 2; mt++) {
                int arow = warp_m * 32 + mt * 16 + r8 + (mi & 1) * 8;
                int ac   = ks * 2 + (mi >> 1);
                ldsm_x4(a[mt], sS + arow * 128 + ((ac ^ (arow & 7)) << 4));
            }
            uint32_t b[8][2];
            #pragma unroll
            for (int np = 0; np < 4; np++) {
                int brow = warp_n * 64 + np * 16 + (mi >> 1) * 8 + r8;
                int bc   = ks * 2 + (mi & 1);
                uint32_t r[4];
                ldsm_x4(r, sS + SB_OFF + brow * 128 + ((bc ^ (brow & 7)) << 4));
                b[np * 2][0]     = r[0]; b[np * 2][1]     = r[1];
                b[np * 2 + 1][0] = r[2]; b[np * 2 + 1][1] = r[3];
            }
            #pragma unroll
            for (int mt = 0; mt < 2; mt++)
                #pragma unroll
                for (int nt = 0; nt < 8; nt++)
                    mma_f16(acc[mt][nt], a[mt], b[nt]);
        }
        __syncthreads();
    }

    int row0 = tileRow + warp_m * 32 + (lane >> 2);
    int col0 = warp_n * 64 + (lane & 3) * 2;
    #pragma unroll
    for (int mt = 0; mt < 2; mt++) {
        int r = row0 + mt * 16;
        #pragma unroll
        for (int nt = 0; nt < 8; nt++) {
            int cc = col0 + nt * 8;
            if (r < N_NODES)
                *(__half2*)&g_Whh[(size_t)r * OUT_F + cc] =
                    __floats2half2_rn(acc[mt][nt][0], acc[mt][nt][1]);
            if (r + 8 < N_NODES)
                *(__half2*)&g_Whh[(size_t)(r + 8) * OUT_F + cc] =
                    __floats2half2_rn(acc[mt][nt][2], acc[mt][nt][3]);
        }
    }
}

// ---------------- dtype detection + CSR side branch ---------------------------
__global__ void detect_kernel(const int* __restrict__ ei) {
    __shared__ int any;
    if (threadIdx.x == 0) any = 0;
    __syncthreads();
    for (int i = threadIdx.x; i < 2048; i += blockDim.x)
        if (ei[2 * i + 1] != 0) any = 1;
    __syncthreads();
    if (threadIdx.x == 0) g_is64 = any ? 0 : 1;
}

__global__ void init_cnt_kernel() {
    int i = blockIdx.x * blockDim.x + threadIdx.x;
    if (i < N_NODES) g_cnt[i] = 0;
}

__device__ __forceinline__ void load_edge(const void* ei, int e, int& s, int& d) {
    if (g_is64) {
        const long long* p = (const long long*)ei;
        s = (int)p[e];
        d = (int)p[NUM_E + e];
    } else {
        const int* p = (const int*)ei;
        s = p[e];
        d = p[NUM_E + e];
    }
}

__global__ __launch_bounds__(256) void hist_kernel(const void* __restrict__ ei) {
    int e = blockIdx.x * blockDim.x + threadIdx.x;
    if (e >= NUM_E) return;
    int s, d;
    load_edge(ei, e, s, d);
    atomicAdd(&g_cnt[s], 1);
}

__global__ __launch_bounds__(256) void scan_reduce_kernel() {
    __shared__ int ws[8];
    int tid = threadIdx.x, lane = tid & 31, wid = tid >> 5;
    int s = 0;
    #pragma unroll
    for (int j = 0; j < 4; j++) {
        int i = blockIdx.x * 1024 + j * 256 + tid;
        if (i < N_NODES) s += g_cnt[i];
    }
    #pragma unroll
    for (int o = 16; o; o >>= 1) s += __shfl_xor_sync(0xFFFFFFFFu, s, o);
    if (lane == 0) ws[wid] = s;
    __syncthreads();
    if (tid == 0) {
        int t = 0;
        #pragma unroll
        for (int w = 0; w < 8; w++) t += ws[w];
        g_bsum[blockIdx.x] = t;
    }
}

__global__ void scan_mid_kernel() {
    __shared__ int w0sum;
    int t = threadIdx.x;            // 64 threads
    int lane = t & 31, w = t >> 5;
    const int NBLK = (N_NODES + 1023) / 1024;   // 49
    int v = (t < NBLK) ? g_bsum[t] : 0;
    int x = v;
    #pragma unroll
    for (int o = 1; o < 32; o <<= 1) {
        int y = __shfl_up_sync(0xFFFFFFFFu, x, o);
        if (lane >= o) x += y;
    }
    if (w == 0 && lane == 31) w0sum = x;
    __syncthreads();
    int incl = x + (w == 1 ? w0sum : 0);
    if (t < NBLK) g_boff[t] = incl - v;   // exclusive
}

__global__ __launch_bounds__(1024) void scan_final_kernel() {
    __shared__ int warpsum[32];
    int tid = threadIdx.x, lane = tid & 31, wid = tid >> 5;
    int i = blockIdx.x * 1024 + tid;
    int v = (i < N_NODES) ? g_cnt[i] : 0;
    int x = v;
    #pragma unroll
    for (int o = 1; o < 32; o <<= 1) {
        int y = __shfl_up_sync(0xFFFFFFFFu, x, o);
        if (lane >= o) x += y;
    }
    if (lane == 31) warpsum[wid] = x;
    __syncthreads();
    if (wid == 0) {
        int s = warpsum[lane];
        #pragma unroll
        for (int o = 1; o < 32; o <<= 1) {
            int y = __shfl_up_sync(0xFFFFFFFFu, s, o);
            if (lane >= o) s += y;
        }
        warpsum[lane] = s;
    }
    __syncthreads();
    int base = (wid > 0) ? warpsum[wid - 1] : 0;
    int excl = g_boff[blockIdx.x] + base + x - v;
    if (i < N_NODES) {
        g_off[i]    = excl;
        g_cursor[i] = excl;
    }
    if (blockIdx.x == 0 && tid == 0) g_off[N_NODES] = NUM_E;
}

// fill: dst only — independent of s1/s2, runs fully in the side branch
__global__ __launch_bounds__(256) void fill_kernel(const void* __restrict__ ei) {
    int e = blockIdx.x * blockDim.x + threadIdx.x;
    if (e >= NUM_E) return;
    int s, d;
    load_edge(ei, e, s, d);
    int pos = atomicAdd(&g_cursor[s], 1);
    g_csr_dst[pos] = d;
}

// ---------------- aggregate: warp per node, half-warp per edge ----------------
// w computed inline: exp(leaky(s1[src] + s2[dst]) * 2)
__global__ __launch_bounds__(256) void agg_kernel(float* __restrict__ out) {
    int src  = blockIdx.x * 8 + (threadIdx.x >> 5);
    if (src >= N_NODES) return;
    int lane = threadIdx.x & 31;
    int l16  = lane & 15;
    int half = (lane >> 4) & 1;
    int beg  = g_off[src];
    int end  = g_off[src + 1];

    float4* out4 = (float4*)out;
    if (beg == end) {
        if (lane < 16) {
            out4[(size_t)src * 32 + l16 * 2]     = make_float4(0.f, 0.f, 0.f, 0.f);
            out4[(size_t)src * 32 + l16 * 2 + 1] = make_float4(0.f, 0.f, 0.f, 0.f);
        }
        return;
    }

    const float s1s = __ldg(&g_s1[src]);

    float acc[8];
    #pragma unroll
    for (int i = 0; i < 8; i++) acc[i] = 0.0f;
    float den = 0.f;

    for (int base = beg; base < end; base += 32) {
        int  idx   = base + lane;
        bool valid = idx < end;
        int   dn = valid ? __ldg(&g_csr_dst[idx]) : 0;
        float w  = 0.0f;
        if (valid)
            w = __expf(leaky_logit(s1s + __ldg(&g_s2[dn])));
        den += w;
        int cnt   = min(end - base, 32);
        int iters = (cnt + 1) >> 1;
        #pragma unroll 4
        for (int j = 0; j < iters; j++) {
            int   sl = 2 * j + half;
            int   dj = __shfl_sync(0xFFFFFFFFu, dn, sl);
            float wj = __shfl_sync(0xFFFFFFFFu, w,  sl);
            uint4 u = __ldg((const uint4*)&g_Whh[(size_t)dj * OUT_F + l16 * 8]);
            float2 f0 = __half22float2(*(__half2*)&u.x);
            float2 f1 = __half22float2(*(__half2*)&u.y);
            float2 f2 = __half22float2(*(__half2*)&u.z);
            float2 f3 = __half22float2(*(__half2*)&u.w);
            acc[0] += wj * f0.x; acc[1] += wj * f0.y;
            acc[2] += wj * f1.x; acc[3] += wj * f1.y;
            acc[4] += wj * f2.x; acc[5] += wj * f2.y;
            acc[6] += wj * f3.x; acc[7] += wj * f3.y;
        }
    }

    // combine halves (same features, disjoint edge subsets)
    #pragma unroll
    for (int i = 0; i < 8; i++)
        acc[i] += __shfl_xor_sync(0xFFFFFFFFu, acc[i], 16);
    #pragma unroll
    for (int o = 16; o; o >>= 1)
        den += __shfl_xor_sync(0xFFFFFFFFu, den, o);
    float inv = (den > 0.0f) ? (1.0f / den) : 0.0f;

    if (lane < 16) {
        float4 r0, r1;
        r0.x = fmaxf(acc[0] * inv, 0.0f); r0.y = fmaxf(acc[1] * inv, 0.0f);
        r0.z = fmaxf(acc[2] * inv, 0.0f); r0.w = fmaxf(acc[3] * inv, 0.0f);
        r1.x = fmaxf(acc[4] * inv, 0.0f); r1.y = fmaxf(acc[5] * inv, 0.0f);
        r1.z = fmaxf(acc[6] * inv, 0.0f); r1.w = fmaxf(acc[7] * inv, 0.0f);
        out4[(size_t)src * 32 + l16 * 2]     = r0;
        out4[(size_t)src * 32 + l16 * 2 + 1] = r1;
    }
}

// ---------------- launch ------------------------------------------------------
extern "C" void kernel_launch(void* const* d_in, const int* in_sizes, int n_in,
                              void* d_out, int out_size) {
    const float* h  = (const float*)d_in[0];
    const float* W  = (const float*)d_in[1];
    const float* a  = (const float*)d_in[2];
    const void*  ei = d_in[3];
    float* out = (float*)d_out;

    static cudaStream_t s2 = nullptr;
    static cudaEvent_t evFork = nullptr, evJoin = nullptr;
    if (s2 == nullptr) {
        cudaStreamCreateWithFlags(&s2, cudaStreamNonBlocking);
        cudaEventCreateWithFlags(&evFork, cudaEventDisableTiming);
        cudaEventCreateWithFlags(&evJoin, cudaEventDisableTiming);
        cudaFuncSetAttribute(gemm_f16_kernel,
                             cudaFuncAttributeMaxDynamicSharedMemorySize, GEMM_SMEM);
    }

    const int NBLK = (N_NODES + 1023) / 1024;   // 49

    cudaEventRecord(evFork, 0);
    cudaStreamWaitEvent(s2, evFork, 0);

    // s2: full CSR build incl. fill (depends only on edge_index)
    detect_kernel<<<1, 256, 0, s2>>>((const int*)ei);
    init_cnt_kernel<<<(N_NODES + 255) / 256, 256, 0, s2>>>();
    hist_kernel<<<(NUM_E + 255) / 256, 256, 0, s2>>>(ei);
    scan_reduce_kernel<<<NBLK, 256, 0, s2>>>();
    scan_mid_kernel<<<1, 64, 0, s2>>>();
    scan_final_kernel<<<NBLK, 1024, 0, s2>>>();
    fill_kernel<<<(NUM_E + 255) / 256, 256, 0, s2>>>(ei);
    cudaEventRecord(evJoin, s2);

    // main: u -> fused convert+matvec -> convert_w -> gemm
    u_kernel<<<(IN_F + 7) / 8, 256>>>(W, a);
    convmv_kernel<<<(PAD_ROWS + 7) / 8, 256>>>(h);
    convert_w_kernel<<<(OUT_F * (IN_F / 8) + 255) / 256, 256>>>(W);
    gemm_f16_kernel<<<N_TILES, 256, GEMM_SMEM>>>();

    // join, then aggregate (needs s1/s2 + Whh from main, CSR from s2)
    cudaStreamWaitEvent(0, evJoin, 0);
    agg_kernel<<<(N_NODES + 7) / 8, 256>>>(out);
}